// round 2
// baseline (speedup 1.0000x reference)
#include <cuda_runtime.h>
#include <math.h>

#define Bn 32
#define Ln 1024
#define En 512
#define Mn 64

// ---------------- scratch (static device globals; no runtime alloc) ----------
__device__ float g_cos[Ln];
__device__ float g_sin[Ln];
// X[b][r][h], r in 0..127: r<64 -> real part of mode r, r>=64 -> imag part of mode r-64
__device__ float g_X[Bn * 2 * Mn * En];
// Z[b][k][i], k=2m -> w_m*Yr, k=2m+1 -> w_m*Yi
__device__ float g_Z[Bn * 2 * Mn * En];
// W transposed to [m][h][i] (coalesced in i)
__device__ float g_Wtr[Mn * En * En];
__device__ float g_Wti[Mn * En * En];

// ---------------- trig table --------------------------------------------------
__global__ void trig_kernel() {
    int j = blockIdx.x * blockDim.x + threadIdx.x;
    if (j < Ln) {
        float s, c;
        // angle = 2*pi*j/L ; sincospif(x) = sin/cos(pi*x), x = j/512 exact in fp32
        sincospif((float)j * (2.0f / (float)Ln), &s, &c);
        g_cos[j] = c;
        g_sin[j] = s;
    }
}

// ---------------- W transpose: W[h][i][m] -> Wt[m][h][i] ----------------------
__global__ __launch_bounds__(256) void wtrans_kernel(const float* __restrict__ wr,
                                                     const float* __restrict__ wi) {
    __shared__ float tile[64][33];
    const float* src = blockIdx.z ? wi : wr;
    float* dst = blockIdx.z ? g_Wti : g_Wtr;
    int h = blockIdx.y;
    int i0 = blockIdx.x * 32;
    int tid = threadIdx.x;
    // read 32 i-rows x 64 contiguous m (8KB contiguous region per block)
    #pragma unroll
    for (int e0 = 0; e0 < 8; e0++) {
        int e = tid + e0 * 256;
        int ii = e >> 6, m = e & 63;
        tile[m][ii] = src[((size_t)h * En + (size_t)(i0 + ii)) * Mn + m];
    }
    __syncthreads();
    // write 64 m-rows x 32 contiguous i (coalesced 128B rows)
    #pragma unroll
    for (int e0 = 0; e0 < 8; e0++) {
        int e = tid + e0 * 256;
        int m = e >> 5, ii = e & 31;
        dst[((size_t)m * En + h) * En + i0 + ii] = tile[m][ii];
    }
}

// ---------------- stage 1: truncated DFT --------------------------------------
// X[b][r][h]: r<64: sum_l q[b,l,h]*cos(2*pi*l*r/L); r>=64: -sum_l q*sin(2*pi*l*(r-64)/L)
__global__ __launch_bounds__(256) void dft_kernel(const float* __restrict__ q) {
    __shared__ float sA[16][64];    // [k][mode-local]
    __shared__ float sB[16][68];    // [k][h-local]
    __shared__ float strig[Ln];     // selected (and pre-signed) trig table

    int tid = threadIdx.x;
    int isin = blockIdx.y;
    {
        const float* t = isin ? g_sin : g_cos;
        float sgn = isin ? -1.0f : 1.0f;
        for (int j = tid; j < Ln; j += 256) strig[j] = sgn * t[j];
    }

    int b = blockIdx.z;
    int h0 = blockIdx.x * 64;
    int r0 = isin * 64;
    int ty = tid >> 4, tx = tid & 15;

    float acc[4][4] = {};
    const float* qb = q + (size_t)b * Ln * En;
    __syncthreads();

    for (int l0 = 0; l0 < Ln; l0 += 16) {
        #pragma unroll
        for (int e0 = 0; e0 < 4; e0++) {
            int e = tid + e0 * 256;
            int k = e >> 6, j = e & 63;
            sB[k][j] = qb[(size_t)(l0 + k) * En + h0 + j];
            sA[k][j] = strig[((l0 + k) * j) & (Ln - 1)];
        }
        __syncthreads();
        #pragma unroll
        for (int k = 0; k < 16; k++) {
            float4 av = *(const float4*)&sA[k][ty * 4];
            float4 bv = *(const float4*)&sB[k][tx * 4];
            float a[4] = {av.x, av.y, av.z, av.w};
            float bb[4] = {bv.x, bv.y, bv.z, bv.w};
            #pragma unroll
            for (int u = 0; u < 4; u++)
                #pragma unroll
                for (int v = 0; v < 4; v++)
                    acc[u][v] += a[u] * bb[v];
        }
        __syncthreads();
    }

    float* Xb = g_X + ((size_t)b * 128 + r0) * En;
    #pragma unroll
    for (int u = 0; u < 4; u++) {
        float4 o = make_float4(acc[u][0], acc[u][1], acc[u][2], acc[u][3]);
        *(float4*)&Xb[(size_t)(ty * 4 + u) * En + h0 + tx * 4] = o;
    }
}

// ---------------- stage 2: per-mode complex GEMM ------------------------------
// Y[b,i,m] = sum_h X[b,h,m] * W[h,i,m]   (complex)
// Z[b][2m][i] = w_m*Yr ; Z[b][2m+1][i] = w_m*Yi,  w_0=1/L, w_m=2/L
__global__ __launch_bounds__(256) void modegemm_kernel() {
    __shared__ float sAr[32][34], sAi[32][34];   // [k][b]
    __shared__ float sBr[32][68], sBi[32][68];   // [k][i-local]

    int tid = threadIdx.x;
    int m = blockIdx.y;
    int i0 = blockIdx.x * 64;
    int ty = tid >> 4, tx = tid & 15;

    float accr[2][4] = {}, acci[2][4] = {};

    const float* Xr = g_X + (size_t)m * En;          // + b*128*En + h
    const float* Xi = g_X + (size_t)(Mn + m) * En;
    const float* Wr = g_Wtr + (size_t)m * En * En;
    const float* Wi = g_Wti + (size_t)m * En * En;

    for (int h0 = 0; h0 < En; h0 += 32) {
        #pragma unroll
        for (int e0 = 0; e0 < 4; e0++) {
            int e = tid + e0 * 256;
            int bb = e >> 5, k = e & 31;
            size_t off = (size_t)bb * 128 * En + h0 + k;
            sAr[k][bb] = Xr[off];
            sAi[k][bb] = Xi[off];
        }
        #pragma unroll
        for (int e0 = 0; e0 < 8; e0++) {
            int e = tid + e0 * 256;
            int k = e >> 6, j = e & 63;
            size_t off = (size_t)(h0 + k) * En + i0 + j;
            sBr[k][j] = Wr[off];
            sBi[k][j] = Wi[off];
        }
        __syncthreads();
        #pragma unroll
        for (int k = 0; k < 32; k++) {
            float2 arv = *(const float2*)&sAr[k][ty * 2];
            float2 aiv = *(const float2*)&sAi[k][ty * 2];
            float4 brv = *(const float4*)&sBr[k][tx * 4];
            float4 biv = *(const float4*)&sBi[k][tx * 4];
            float ar[2] = {arv.x, arv.y};
            float ai[2] = {aiv.x, aiv.y};
            float br[4] = {brv.x, brv.y, brv.z, brv.w};
            float bi[4] = {biv.x, biv.y, biv.z, biv.w};
            #pragma unroll
            for (int u = 0; u < 2; u++)
                #pragma unroll
                for (int v = 0; v < 4; v++) {
                    accr[u][v] += ar[u] * br[v];
                    accr[u][v] -= ai[u] * bi[v];
                    acci[u][v] += ar[u] * bi[v];
                    acci[u][v] += ai[u] * br[v];
                }
        }
        __syncthreads();
    }

    float w = (m == 0 ? 1.0f : 2.0f) / (float)Ln;
    #pragma unroll
    for (int u = 0; u < 2; u++) {
        int bb = ty * 2 + u;
        float* Zb = g_Z + ((size_t)bb * 128 + 2 * m) * En + i0 + tx * 4;
        float4 zr = make_float4(w * accr[u][0], w * accr[u][1], w * accr[u][2], w * accr[u][3]);
        float4 zi = make_float4(w * acci[u][0], w * acci[u][1], w * acci[u][2], w * acci[u][3]);
        *(float4*)Zb = zr;
        *(float4*)(Zb + En) = zi;
    }
}

// ---------------- stage 3: truncated inverse DFT ------------------------------
// out[b,l,i] = sum_{k=0}^{127} C[l,k] * Z[b,k,i]
// C[l,2m] = cos(2*pi*l*m/L), C[l,2m+1] = -sin(2*pi*l*m/L)  (weights already in Z)
__global__ __launch_bounds__(256) void irfft_kernel(float* __restrict__ out) {
    __shared__ float sA[32][64];    // [k][l-local]
    __shared__ float sB[32][68];    // [k][i-local]
    __shared__ float sc[Ln];
    __shared__ float ssn[Ln];

    int tid = threadIdx.x;
    for (int j = tid; j < Ln; j += 256) { sc[j] = g_cos[j]; ssn[j] = g_sin[j]; }

    int b = blockIdx.z;
    int l0 = blockIdx.y * 64;
    int i0 = blockIdx.x * 64;
    int ty = tid >> 4, tx = tid & 15;

    float acc[4][4] = {};
    const float* Zb = g_Z + (size_t)b * 128 * En;
    __syncthreads();

    for (int k0 = 0; k0 < 128; k0 += 32) {
        #pragma unroll
        for (int e0 = 0; e0 < 8; e0++) {
            int e = tid + e0 * 256;
            int k = e >> 6, r = e & 63;
            int kk = k0 + k;
            int mm = kk >> 1;
            int idx = ((l0 + r) * mm) & (Ln - 1);
            sA[k][r] = (kk & 1) ? -ssn[idx] : sc[idx];
        }
        #pragma unroll
        for (int e0 = 0; e0 < 8; e0++) {
            int e = tid + e0 * 256;
            int k = e >> 6, j = e & 63;
            sB[k][j] = Zb[(size_t)(k0 + k) * En + i0 + j];
        }
        __syncthreads();
        #pragma unroll
        for (int k = 0; k < 32; k++) {
            float4 av = *(const float4*)&sA[k][ty * 4];
            float4 bv = *(const float4*)&sB[k][tx * 4];
            float a[4] = {av.x, av.y, av.z, av.w};
            float bb[4] = {bv.x, bv.y, bv.z, bv.w};
            #pragma unroll
            for (int u = 0; u < 4; u++)
                #pragma unroll
                for (int v = 0; v < 4; v++)
                    acc[u][v] += a[u] * bb[v];
        }
        __syncthreads();
    }

    float* ob = out + ((size_t)b * Ln + l0) * En;
    #pragma unroll
    for (int u = 0; u < 4; u++) {
        float4 o = make_float4(acc[u][0], acc[u][1], acc[u][2], acc[u][3]);
        *(float4*)&ob[(size_t)(ty * 4 + u) * En + i0 + tx * 4] = o;
    }
}

// ---------------- launch ------------------------------------------------------
extern "C" void kernel_launch(void* const* d_in, const int* in_sizes, int n_in,
                              void* d_out, int out_size) {
    (void)in_sizes; (void)n_in; (void)out_size;
    const float* q  = (const float*)d_in[0];
    const float* wr = (const float*)d_in[1];
    const float* wi = (const float*)d_in[2];
    float* out = (float*)d_out;

    trig_kernel<<<4, 256>>>();
    wtrans_kernel<<<dim3(16, 512, 2), 256>>>(wr, wi);
    dft_kernel<<<dim3(8, 2, 32), 256>>>(q);
    modegemm_kernel<<<dim3(8, 64), 256>>>();
    irfft_kernel<<<dim3(8, 16, 32), 256>>>(out);
}